// round 1
// baseline (speedup 1.0000x reference)
#include <cuda_runtime.h>
#include <cstdint>

#define N_COLS 24576
#define K_TOP 64
#define THREADS 512
#define F4_PER_THREAD 12   // 24576 / 4 / 512
#define NBINS 2048
#define CAP 4096

// Monotonic key: larger float -> larger unsigned key
__device__ __forceinline__ unsigned fkey(float x) {
    unsigned u = __float_as_uint(x);
    return (u & 0x80000000u) ? ~u : (u | 0x80000000u);
}

__global__ __launch_bounds__(THREADS, 1)
void topk_act_kernel(const float* __restrict__ x, float* __restrict__ out) {
    __shared__ unsigned hist[NBINS];
    __shared__ unsigned candKey[CAP];
    __shared__ unsigned candIdx[CAP];
    __shared__ unsigned s_ncand;
    __shared__ unsigned s_thrBin;
    __shared__ unsigned s_nAbove;
    __shared__ unsigned s_kthKey;
    __shared__ unsigned s_cutIdx;

    const int row = blockIdx.x;
    const float4* __restrict__ xr = (const float4*)(x + (size_t)row * N_COLS);
    float4* __restrict__ orow = (float4*)(out + (size_t)row * N_COLS);
    const int tid = threadIdx.x;
    const int lane = tid & 31;

    for (int i = tid; i < NBINS; i += THREADS) hist[i] = 0;
    if (tid == 0) s_ncand = 0;
    __syncthreads();

    // ---- Load row into registers (coalesced float4) ----
    float4 v[F4_PER_THREAD];
    #pragma unroll
    for (int i = 0; i < F4_PER_THREAD; i++)
        v[i] = xr[tid + i * THREADS];

    // ---- Stage 1: 2048-bin histogram of top 11 key bits, warp-aggregated ----
    #pragma unroll
    for (int i = 0; i < F4_PER_THREAD; i++) {
        float vals[4] = {v[i].x, v[i].y, v[i].z, v[i].w};
        #pragma unroll
        for (int c = 0; c < 4; c++) {
            unsigned bin = fkey(vals[c]) >> 21;
            unsigned m = __match_any_sync(0xffffffffu, bin);
            if ((__ffs(m) - 1) == lane)
                atomicAdd(&hist[bin], __popc(m));
        }
    }
    __syncthreads();

    // ---- Stage 2: warp 0 finds the bin containing the K-th largest key ----
    if (tid < 32) {
        unsigned cum = 0;
        for (int chunk = 0; chunk < NBINS / 32; chunk++) {
            int b = NBINS - 1 - (chunk * 32 + lane);   // lane 0 = highest bin
            unsigned c = hist[b];
            unsigned s = c;
            #pragma unroll
            for (int o = 1; o < 32; o <<= 1) {
                unsigned t = __shfl_up_sync(0xffffffffu, s, o);
                if (lane >= o) s += t;
            }
            unsigned total = __shfl_sync(0xffffffffu, s, 31);
            if (cum + total >= K_TOP || chunk == NBINS / 32 - 1) {
                unsigned ballot = __ballot_sync(0xffffffffu, cum + s >= K_TOP);
                int sel = __ffs(ballot) - 1;
                if (sel < 0) sel = 31;          // pathological fallback
                if (lane == sel) {
                    s_thrBin = (unsigned)b;
                    s_nAbove = cum + s - c;     // strictly above this bin
                }
                break;
            }
            cum += total;
        }
    }
    __syncthreads();
    const unsigned thrBin = s_thrBin;

    // ---- Stage 3: collect candidates from the threshold bin ----
    #pragma unroll
    for (int i = 0; i < F4_PER_THREAD; i++) {
        float vals[4] = {v[i].x, v[i].y, v[i].z, v[i].w};
        #pragma unroll
        for (int c = 0; c < 4; c++) {
            unsigned key = fkey(vals[c]);
            if ((key >> 21) == thrBin) {
                unsigned p = atomicAdd(&s_ncand, 1u);
                if (p < CAP) {
                    candKey[p] = key;
                    candIdx[p] = (unsigned)((tid + i * THREADS) * 4 + c);
                }
            }
        }
    }
    __syncthreads();

    // ---- Stage 4: warp 0 computes the exact K-th key + tie index cutoff ----
    if (tid < 32) {
        int nc = (int)min(s_ncand, (unsigned)CAP);
        int need = K_TOP - (int)s_nAbove;   // 1..K_TOP, guaranteed >= 1

        // kth key = min key among candidates with (count greater) < need
        unsigned bestKey = 0xffffffffu;
        for (int j = lane; j < nc; j += 32) {
            unsigned kj = candKey[j];
            int gt = 0;
            for (int q = 0; q < nc; q++) gt += (candKey[q] > kj);
            if (gt < need) bestKey = min(bestKey, kj);
        }
        #pragma unroll
        for (int o = 16; o; o >>= 1)
            bestKey = min(bestKey, __shfl_xor_sync(0xffffffffu, bestKey, o));

        // count strictly greater than kth key (within bin)
        int ngt = 0;
        for (int j = lane; j < nc; j += 32) ngt += (candKey[j] > bestKey);
        #pragma unroll
        for (int o = 16; o; o >>= 1) ngt += __shfl_xor_sync(0xffffffffu, ngt, o);
        int need_eq = need - ngt;           // >= 1

        // among ties at kth key, keep the need_eq smallest indices (jax tie-break)
        unsigned cut = 0xffffffffu;
        for (int j = lane; j < nc; j += 32) {
            if (candKey[j] == bestKey) {
                unsigned ij = candIdx[j];
                int lt = 0;
                for (int q = 0; q < nc; q++)
                    lt += (candKey[q] == bestKey && candIdx[q] < ij);
                if (lt == need_eq - 1) cut = ij;
            }
        }
        #pragma unroll
        for (int o = 16; o; o >>= 1)
            cut = min(cut, __shfl_xor_sync(0xffffffffu, cut, o));

        if (lane == 0) { s_kthKey = bestKey; s_cutIdx = cut; }
    }
    __syncthreads();

    const unsigned kth = s_kthKey;
    const unsigned cut = s_cutIdx;

    // ---- Stage 5: write output from registers ----
    #pragma unroll
    for (int i = 0; i < F4_PER_THREAD; i++) {
        float vals[4] = {v[i].x, v[i].y, v[i].z, v[i].w};
        float res[4];
        #pragma unroll
        for (int c = 0; c < 4; c++) {
            unsigned key = fkey(vals[c]);
            unsigned idx = (unsigned)((tid + i * THREADS) * 4 + c);
            bool sel = (key > kth) || (key == kth && idx <= cut);
            res[c] = sel ? fmaxf(vals[c], 0.0f) : 0.0f;
        }
        float4 o4 = make_float4(res[0], res[1], res[2], res[3]);
        orow[tid + i * THREADS] = o4;
    }
}

extern "C" void kernel_launch(void* const* d_in, const int* in_sizes, int n_in,
                              void* d_out, int out_size) {
    const float* x = (const float*)d_in[0];
    float* out = (float*)d_out;
    int rows = in_sizes[0] / N_COLS;   // 8192
    topk_act_kernel<<<rows, THREADS>>>(x, out);
}

// round 2
// speedup vs baseline: 1.1259x; 1.1259x over previous
#include <cuda_runtime.h>
#include <cstdint>

#define N_COLS 24576
#define K_TOP 64
#define THREADS 512
#define F4_PER_THREAD 12   // 24576 / 4 / 512
#define NBINS 2048
#define NCHUNK 16          // = warps per CTA
#define CAP 2048

// Monotonic key: larger float -> larger unsigned key
__device__ __forceinline__ unsigned fkey(float x) {
    unsigned u = __float_as_uint(x);
    return (u & 0x80000000u) ? ~u : (u | 0x80000000u);
}

__global__ __launch_bounds__(THREADS, 3)
void topk_act_kernel(const float* __restrict__ x, float* __restrict__ out) {
    __shared__ unsigned hist[NBINS];
    __shared__ unsigned chunkTot[NCHUNK];
    __shared__ unsigned chunkPref[NCHUNK];
    __shared__ unsigned candKey[CAP];
    __shared__ unsigned candIdx[CAP];
    __shared__ unsigned s_ncand;
    __shared__ unsigned s_thrBin;
    __shared__ unsigned s_nAbove;
    __shared__ unsigned s_kthKey;
    __shared__ unsigned s_cutIdx;

    const int row = blockIdx.x;
    const float4* __restrict__ xr = (const float4*)(x + (size_t)row * N_COLS);
    float4* __restrict__ orow = (float4*)(out + (size_t)row * N_COLS);
    const int tid = threadIdx.x;
    const int lane = tid & 31;
    const int wid = tid >> 5;

    for (int i = tid; i < NBINS; i += THREADS) hist[i] = 0;
    if (tid == 0) s_ncand = 0;
    __syncthreads();

    // ---- Stage 1: stream row from DRAM, 2048-bin histogram (warp-aggregated) ----
    #pragma unroll
    for (int i = 0; i < F4_PER_THREAD; i++) {
        float4 v = xr[tid + i * THREADS];
        float vals[4] = {v.x, v.y, v.z, v.w};
        #pragma unroll
        for (int c = 0; c < 4; c++) {
            unsigned bin = fkey(vals[c]) >> 21;
            unsigned m = __match_any_sync(0xffffffffu, bin);
            if ((unsigned)(__ffs(m) - 1) == (unsigned)lane)
                atomicAdd(&hist[bin], __popc(m));
        }
    }
    __syncthreads();

    // ---- Stage 2: all-warp 2-level descending scan to find threshold bin ----
    // Warp w owns 128 bins: descending order positions [w*128, w*128+128)
    unsigned cnt[4];
    unsigned mySum = 0;
    #pragma unroll
    for (int j = 0; j < 4; j++) {
        cnt[j] = hist[NBINS - 1 - (wid * 128 + lane * 4 + j)];
        mySum += cnt[j];
    }
    unsigned wtot = mySum;
    #pragma unroll
    for (int o = 16; o; o >>= 1) wtot += __shfl_xor_sync(0xffffffffu, wtot, o);
    if (lane == 0) chunkTot[wid] = wtot;
    __syncthreads();
    if (tid == 0) {
        unsigned acc = 0;
        for (int w = 0; w < NCHUNK; w++) { chunkPref[w] = acc; acc += chunkTot[w]; }
    }
    __syncthreads();
    {
        unsigned pref = chunkPref[wid];
        if (pref < K_TOP && pref + chunkTot[wid] >= K_TOP) {
            // this warp contains the crossing; warp-inclusive scan of lane sums
            unsigned inc = mySum;
            #pragma unroll
            for (int o = 1; o < 32; o <<= 1) {
                unsigned t = __shfl_up_sync(0xffffffffu, inc, o);
                if (lane >= o) inc += t;
            }
            unsigned ball = __ballot_sync(0xffffffffu, pref + inc >= K_TOP);
            int sel = __ffs(ball) - 1;
            if (lane == sel) {
                unsigned cum = pref + inc - mySum;   // count strictly above this lane's bins
                #pragma unroll
                for (int j = 0; j < 4; j++) {
                    if (cum + cnt[j] >= K_TOP) {
                        s_thrBin = (unsigned)(NBINS - 1 - (wid * 128 + lane * 4 + j));
                        s_nAbove = cum;
                        break;
                    }
                    cum += cnt[j];
                }
            }
        }
    }
    __syncthreads();
    const unsigned thrBin = s_thrBin;

    // ---- Stage 3: re-read row (L2 hits), collect candidates in threshold bin ----
    #pragma unroll
    for (int i = 0; i < F4_PER_THREAD; i++) {
        float4 v = xr[tid + i * THREADS];
        float vals[4] = {v.x, v.y, v.z, v.w};
        #pragma unroll
        for (int c = 0; c < 4; c++) {
            unsigned key = fkey(vals[c]);
            if ((key >> 21) == thrBin) {
                unsigned p = atomicAdd(&s_ncand, 1u);
                if (p < CAP) {
                    candKey[p] = key;
                    candIdx[p] = (unsigned)((tid + i * THREADS) * 4 + c);
                }
            }
        }
    }
    __syncthreads();

    // ---- Stage 4: warp 0 computes exact K-th key + tie index cutoff ----
    if (tid < 32) {
        int nc = (int)min(s_ncand, (unsigned)CAP);
        int need = K_TOP - (int)s_nAbove;   // 1..K_TOP

        unsigned bestKey = 0xffffffffu;
        for (int j = lane; j < nc; j += 32) {
            unsigned kj = candKey[j];
            int gt = 0;
            for (int q = 0; q < nc; q++) gt += (candKey[q] > kj);
            if (gt < need) bestKey = min(bestKey, kj);
        }
        #pragma unroll
        for (int o = 16; o; o >>= 1)
            bestKey = min(bestKey, __shfl_xor_sync(0xffffffffu, bestKey, o));

        int ngt = 0;
        for (int j = lane; j < nc; j += 32) ngt += (candKey[j] > bestKey);
        #pragma unroll
        for (int o = 16; o; o >>= 1) ngt += __shfl_xor_sync(0xffffffffu, ngt, o);
        int need_eq = need - ngt;           // >= 1

        unsigned cut = 0xffffffffu;
        for (int j = lane; j < nc; j += 32) {
            if (candKey[j] == bestKey) {
                unsigned ij = candIdx[j];
                int lt = 0;
                for (int q = 0; q < nc; q++)
                    lt += (candKey[q] == bestKey && candIdx[q] < ij);
                if (lt == need_eq - 1) cut = ij;
            }
        }
        #pragma unroll
        for (int o = 16; o; o >>= 1)
            cut = min(cut, __shfl_xor_sync(0xffffffffu, cut, o));

        if (lane == 0) { s_kthKey = bestKey; s_cutIdx = cut; }
    }
    __syncthreads();

    const unsigned kth = s_kthKey;
    const unsigned cut = s_cutIdx;

    // ---- Stage 5: re-read row (L2 hits), apply threshold + relu, write out ----
    #pragma unroll
    for (int i = 0; i < F4_PER_THREAD; i++) {
        float4 v = xr[tid + i * THREADS];
        float vals[4] = {v.x, v.y, v.z, v.w};
        float res[4];
        #pragma unroll
        for (int c = 0; c < 4; c++) {
            unsigned key = fkey(vals[c]);
            unsigned idx = (unsigned)((tid + i * THREADS) * 4 + c);
            bool sel = (key > kth) || (key == kth && idx <= cut);
            res[c] = sel ? fmaxf(vals[c], 0.0f) : 0.0f;
        }
        orow[tid + i * THREADS] = make_float4(res[0], res[1], res[2], res[3]);
    }
}

extern "C" void kernel_launch(void* const* d_in, const int* in_sizes, int n_in,
                              void* d_out, int out_size) {
    const float* x = (const float*)d_in[0];
    float* out = (float*)d_out;
    int rows = in_sizes[0] / N_COLS;   // 8192
    topk_act_kernel<<<rows, THREADS>>>(x, out);
}

// round 3
// speedup vs baseline: 4.4113x; 3.9178x over previous
#include <cuda_runtime.h>
#include <cstdint>

#define N_COLS 24576
#define K_TOP 64
#define THREADS 512
#define F4_PER_THREAD 12   // 24576 / 4 / 512
#define NBINS 2048
#define NCHUNK 16          // warps per CTA
#define CAP 1024
#define T0 2.2f

// Monotonic key: larger float -> larger unsigned key
__device__ __forceinline__ unsigned fkey(float x) {
    unsigned u = __float_as_uint(x);
    return (u & 0x80000000u) ? ~u : (u | 0x80000000u);
}

__global__ __launch_bounds__(THREADS, 3)
void topk_act_kernel(const float* __restrict__ x, float* __restrict__ out) {
    __shared__ unsigned hist[NBINS];
    __shared__ unsigned chunkTot[NCHUNK], chunkPref[NCHUNK];
    __shared__ unsigned candKey[CAP], candIdx[CAP];
    __shared__ unsigned s_ncand, s_maxKey, s_thrBin, s_nAbove, s_kthKey, s_cutIdx;

    const int row = blockIdx.x;
    const float4* __restrict__ xr = (const float4*)(x + (size_t)row * N_COLS);
    float4* __restrict__ orow = (float4*)(out + (size_t)row * N_COLS);
    float* __restrict__ orow_f = (float*)(out + (size_t)row * N_COLS);
    const int tid = threadIdx.x;
    const int lane = tid & 31;
    const int wid = tid >> 5;

    if (tid == 0) { s_ncand = 0; s_maxKey = 0; }
    __syncthreads();

    const unsigned T0KEY = fkey(T0);

    // ---- Pass 1 (fused): read row, write zeros, collect candidates > T0 ----
    #pragma unroll
    for (int i = 0; i < F4_PER_THREAD; i++) {
        float4 v = xr[tid + i * THREADS];
        orow[tid + i * THREADS] = make_float4(0.f, 0.f, 0.f, 0.f);
        float vals[4] = {v.x, v.y, v.z, v.w};
        #pragma unroll
        for (int c = 0; c < 4; c++) {
            unsigned key = fkey(vals[c]);
            if (key > T0KEY) {
                unsigned p = atomicAdd(&s_ncand, 1u);
                if (p < CAP) {
                    candKey[p] = key;
                    candIdx[p] = (unsigned)((tid + i * THREADS) * 4 + c);
                }
            }
        }
    }
    __syncthreads();
    const unsigned nc = s_ncand;

    if (nc >= K_TOP && nc <= THREADS) {
        // ================= FAST PATH =================
        unsigned myKey = (tid < (int)nc) ? candKey[tid] : 0u;
        unsigned myIdx = (tid < (int)nc) ? candIdx[tid] : 0u;

        // block max of candidate keys (upper bound for search)
        unsigned wmax = myKey;
        #pragma unroll
        for (int o = 16; o; o >>= 1)
            wmax = max(wmax, __shfl_xor_sync(0xffffffffu, wmax, o));
        if (lane == 0) atomicMax(&s_maxKey, wmax);
        __syncthreads();

        // binary search: smallest T with count(key > T) < K  ==> T = kth key
        unsigned lo = T0KEY, hi = s_maxKey;
        while (lo < hi) {
            unsigned mid = lo + ((hi - lo) >> 1);
            int cnt = __syncthreads_count(myKey > mid);
            if (cnt < K_TOP) hi = mid; else lo = mid + 1;
        }
        const unsigned kth = lo;

        int cntGt = __syncthreads_count(myKey > kth);
        int needEq = K_TOP - cntGt;                    // >= 1
        int cntEq = __syncthreads_count(myKey == kth);

        unsigned cut = 0xffffffffu;                    // select all ties
        if (cntEq > needEq) {
            // keep the needEq smallest indices among ties (jax tie-break)
            unsigned l2 = 0, h2 = N_COLS - 1;
            while (l2 < h2) {
                unsigned m2 = l2 + ((h2 - l2) >> 1);
                int c2 = __syncthreads_count(myKey == kth && myIdx <= m2);
                if (c2 >= needEq) h2 = m2; else l2 = m2 + 1;
            }
            cut = l2;
        }

        // scatter winners (all > T0 > 0, so relu is identity)
        if (tid < (int)nc && (myKey > kth || (myKey == kth && myIdx <= cut)))
            orow_f[myIdx] = __uint_as_float(myKey & 0x7fffffffu);

    } else {
        // ================= FALLBACK (exact, slow, ~never taken) =================
        for (int i = tid; i < NBINS; i += THREADS) hist[i] = 0;
        if (tid == 0) s_ncand = 0;
        __syncthreads();

        // histogram of top 11 key bits
        #pragma unroll
        for (int i = 0; i < F4_PER_THREAD; i++) {
            float4 v = xr[tid + i * THREADS];
            float vals[4] = {v.x, v.y, v.z, v.w};
            #pragma unroll
            for (int c = 0; c < 4; c++)
                atomicAdd(&hist[fkey(vals[c]) >> 21], 1u);
        }
        __syncthreads();

        // 2-level descending scan to find threshold bin
        unsigned cnt4[4];
        unsigned mySum = 0;
        #pragma unroll
        for (int j = 0; j < 4; j++) {
            cnt4[j] = hist[NBINS - 1 - (wid * 128 + lane * 4 + j)];
            mySum += cnt4[j];
        }
        unsigned wtot = mySum;
        #pragma unroll
        for (int o = 16; o; o >>= 1) wtot += __shfl_xor_sync(0xffffffffu, wtot, o);
        if (lane == 0) chunkTot[wid] = wtot;
        __syncthreads();
        if (tid == 0) {
            unsigned acc = 0;
            for (int w = 0; w < NCHUNK; w++) { chunkPref[w] = acc; acc += chunkTot[w]; }
        }
        __syncthreads();
        {
            unsigned pref = chunkPref[wid];
            if (pref < K_TOP && pref + chunkTot[wid] >= K_TOP) {
                unsigned inc = mySum;
                #pragma unroll
                for (int o = 1; o < 32; o <<= 1) {
                    unsigned t = __shfl_up_sync(0xffffffffu, inc, o);
                    if (lane >= o) inc += t;
                }
                unsigned ball = __ballot_sync(0xffffffffu, pref + inc >= K_TOP);
                int sel = __ffs(ball) - 1;
                if (lane == sel) {
                    unsigned cum = pref + inc - mySum;
                    #pragma unroll
                    for (int j = 0; j < 4; j++) {
                        if (cum + cnt4[j] >= K_TOP) {
                            s_thrBin = (unsigned)(NBINS - 1 - (wid * 128 + lane * 4 + j));
                            s_nAbove = cum;
                            break;
                        }
                        cum += cnt4[j];
                    }
                }
            }
        }
        __syncthreads();
        const unsigned thrBin = s_thrBin;

        // collect candidates from threshold bin
        #pragma unroll
        for (int i = 0; i < F4_PER_THREAD; i++) {
            float4 v = xr[tid + i * THREADS];
            float vals[4] = {v.x, v.y, v.z, v.w};
            #pragma unroll
            for (int c = 0; c < 4; c++) {
                unsigned key = fkey(vals[c]);
                if ((key >> 21) == thrBin) {
                    unsigned p = atomicAdd(&s_ncand, 1u);
                    if (p < CAP) {
                        candKey[p] = key;
                        candIdx[p] = (unsigned)((tid + i * THREADS) * 4 + c);
                    }
                }
            }
        }
        __syncthreads();

        // warp 0: exact kth + tie cutoff
        if (tid < 32) {
            int ncf = (int)min(s_ncand, (unsigned)CAP);
            int need = K_TOP - (int)s_nAbove;

            unsigned bestKey = 0xffffffffu;
            for (int j = lane; j < ncf; j += 32) {
                unsigned kj = candKey[j];
                int gt = 0;
                for (int q = 0; q < ncf; q++) gt += (candKey[q] > kj);
                if (gt < need) bestKey = min(bestKey, kj);
            }
            #pragma unroll
            for (int o = 16; o; o >>= 1)
                bestKey = min(bestKey, __shfl_xor_sync(0xffffffffu, bestKey, o));

            int ngt = 0;
            for (int j = lane; j < ncf; j += 32) ngt += (candKey[j] > bestKey);
            #pragma unroll
            for (int o = 16; o; o >>= 1) ngt += __shfl_xor_sync(0xffffffffu, ngt, o);
            int need_eq = need - ngt;

            unsigned cut = 0xffffffffu;
            for (int j = lane; j < ncf; j += 32) {
                if (candKey[j] == bestKey) {
                    unsigned ij = candIdx[j];
                    int lt = 0;
                    for (int q = 0; q < ncf; q++)
                        lt += (candKey[q] == bestKey && candIdx[q] < ij);
                    if (lt == need_eq - 1) cut = ij;
                }
            }
            #pragma unroll
            for (int o = 16; o; o >>= 1)
                cut = min(cut, __shfl_xor_sync(0xffffffffu, cut, o));

            if (lane == 0) { s_kthKey = bestKey; s_cutIdx = cut; }
        }
        __syncthreads();

        const unsigned kth = s_kthKey;
        const unsigned cut = s_cutIdx;

        // re-read row (L2 hits), scatter winners with relu
        #pragma unroll
        for (int i = 0; i < F4_PER_THREAD; i++) {
            float4 v = xr[tid + i * THREADS];
            float vals[4] = {v.x, v.y, v.z, v.w};
            #pragma unroll
            for (int c = 0; c < 4; c++) {
                unsigned key = fkey(vals[c]);
                unsigned idx = (unsigned)((tid + i * THREADS) * 4 + c);
                if (key > kth || (key == kth && idx <= cut))
                    orow_f[idx] = fmaxf(vals[c], 0.0f);
            }
        }
    }
}

extern "C" void kernel_launch(void* const* d_in, const int* in_sizes, int n_in,
                              void* d_out, int out_size) {
    const float* x = (const float*)d_in[0];
    float* out = (float*)d_out;
    int rows = in_sizes[0] / N_COLS;   // 8192
    topk_act_kernel<<<rows, THREADS>>>(x, out);
}

// round 4
// speedup vs baseline: 4.6610x; 1.0566x over previous
#include <cuda_runtime.h>
#include <cstdint>

#define N_COLS 24576
#define K_TOP 64
#define THREADS 512
#define F4_PER_THREAD 12   // 24576 / 4 / 512
#define NBINS_F 4096       // fast-path candidate histogram
#define NBINS_S 2048       // fallback full-row histogram
#define NCHUNK 16          // warps per CTA
#define CAP 512
#define T0 2.2f

// Monotonic key: larger float -> larger unsigned key
__device__ __forceinline__ unsigned fkey(float x) {
    unsigned u = __float_as_uint(x);
    return (u & 0x80000000u) ? ~u : (u | 0x80000000u);
}

__global__ __launch_bounds__(THREADS, 3)
void topk_act_kernel(const float* __restrict__ x, float* __restrict__ out) {
    __shared__ unsigned hist[NBINS_F];
    __shared__ unsigned chunkTot[NCHUNK], chunkPref[NCHUNK];
    __shared__ unsigned candKey[CAP], candIdx[CAP];
    __shared__ unsigned eqKey[CAP], eqIdx[CAP];
    __shared__ unsigned s_ncand, s_n2, s_maxKey, s_thrBin, s_nAbove, s_kthKey, s_cutIdx;

    const int row = blockIdx.x;
    const float4* __restrict__ xr = (const float4*)(x + (size_t)row * N_COLS);
    float4* __restrict__ orow = (float4*)(out + (size_t)row * N_COLS);
    float* __restrict__ orow_f = (float*)(out + (size_t)row * N_COLS);
    const int tid = threadIdx.x;
    const int lane = tid & 31;
    const int wid = tid >> 5;

    for (int i = tid; i < NBINS_F; i += THREADS) hist[i] = 0;
    if (tid == 0) { s_ncand = 0; s_n2 = 0; s_maxKey = 0; }
    __syncthreads();

    const unsigned T0KEY = fkey(T0);

    // ---- Pass 1 (fused): read row, write zeros, collect candidates x > T0 ----
    // Common case is pure float compares; fkey only on the ~341 hits per row.
    #pragma unroll
    for (int i = 0; i < F4_PER_THREAD; i++) {
        float4 v = xr[tid + i * THREADS];
        orow[tid + i * THREADS] = make_float4(0.f, 0.f, 0.f, 0.f);
        float m01 = fmaxf(v.x, v.y), m23 = fmaxf(v.z, v.w);
        if (fmaxf(m01, m23) > T0) {
            float vals[4] = {v.x, v.y, v.z, v.w};
            #pragma unroll
            for (int c = 0; c < 4; c++) {
                if (vals[c] > T0) {
                    unsigned key = fkey(vals[c]);
                    unsigned p = atomicAdd(&s_ncand, 1u);
                    if (p < CAP) {
                        candKey[p] = key;
                        candIdx[p] = (unsigned)((tid + i * THREADS) * 4 + c);
                    }
                    atomicMax(&s_maxKey, key);
                }
            }
        }
    }
    __syncthreads();
    const unsigned nc = s_ncand;

    if (nc >= K_TOP && nc <= CAP) {
        // ================= FAST PATH =================
        const unsigned myKey = (tid < (int)nc) ? candKey[tid] : 0u;
        const unsigned myIdx = (tid < (int)nc) ? candIdx[tid] : 0u;
        const bool hasC = (tid < (int)nc);

        // shift so (maxKey - T0KEY) >> shift fits in NBINS_F bins
        unsigned range = s_maxKey - T0KEY;
        int bits = 32 - __clz(range | 1u);
        int shift = bits > 12 ? bits - 12 : 0;
        const unsigned myBin = hasC ? ((myKey - T0KEY) >> shift) : 0u;

        // histogram of candidates
        if (hasC) atomicAdd(&hist[myBin], 1u);
        __syncthreads();

        // descending 2-level scan: thread t owns positions [8t, 8t+8), pos p -> bin 4095-p
        unsigned cnt8[8];
        unsigned mySum = 0;
        #pragma unroll
        for (int j = 0; j < 8; j++) {
            cnt8[j] = hist[NBINS_F - 1 - (tid * 8 + j)];
            mySum += cnt8[j];
        }
        unsigned wtot = mySum;
        #pragma unroll
        for (int o = 16; o; o >>= 1) wtot += __shfl_xor_sync(0xffffffffu, wtot, o);
        if (lane == 0) chunkTot[wid] = wtot;
        __syncthreads();
        if (tid == 0) {
            unsigned acc = 0;
            for (int w = 0; w < NCHUNK; w++) { chunkPref[w] = acc; acc += chunkTot[w]; }
        }
        __syncthreads();
        {
            unsigned pref = chunkPref[wid];
            if (pref < K_TOP && pref + chunkTot[wid] >= K_TOP) {
                unsigned inc = mySum;
                #pragma unroll
                for (int o = 1; o < 32; o <<= 1) {
                    unsigned t = __shfl_up_sync(0xffffffffu, inc, o);
                    if (lane >= o) inc += t;
                }
                unsigned ball = __ballot_sync(0xffffffffu, pref + inc >= K_TOP);
                int sel = __ffs(ball) - 1;
                if (lane == sel) {
                    unsigned cum = pref + inc - mySum;
                    #pragma unroll
                    for (int j = 0; j < 8; j++) {
                        if (cum + cnt8[j] >= K_TOP) {
                            s_thrBin = (unsigned)(NBINS_F - 1 - (tid * 8 + j));
                            s_nAbove = cum;
                            break;
                        }
                        cum += cnt8[j];
                    }
                }
            }
        }
        __syncthreads();

        // gather candidates in the threshold bin (typically 1-3)
        if (hasC && myBin == s_thrBin) {
            unsigned p = atomicAdd(&s_n2, 1u);
            eqKey[p] = myKey;
            eqIdx[p] = myIdx;
        }
        __syncthreads();

        // warp 0: exact kth + tie index cutoff among the in-bin set
        if (tid < 32) {
            int m = (int)s_n2;
            int need = K_TOP - (int)s_nAbove;   // >= 1

            unsigned bestKey = 0xffffffffu;
            for (int j = lane; j < m; j += 32) {
                unsigned kj = eqKey[j];
                int gt = 0;
                for (int q = 0; q < m; q++) gt += (eqKey[q] > kj);
                if (gt < need) bestKey = min(bestKey, kj);
            }
            #pragma unroll
            for (int o = 16; o; o >>= 1)
                bestKey = min(bestKey, __shfl_xor_sync(0xffffffffu, bestKey, o));

            int ngt = 0;
            for (int j = lane; j < m; j += 32) ngt += (eqKey[j] > bestKey);
            #pragma unroll
            for (int o = 16; o; o >>= 1) ngt += __shfl_xor_sync(0xffffffffu, ngt, o);
            int need_eq = need - ngt;           // >= 1

            unsigned cut = 0xffffffffu;
            int neq = 0;
            for (int j = lane; j < m; j += 32) neq += (eqKey[j] == bestKey);
            #pragma unroll
            for (int o = 16; o; o >>= 1) neq += __shfl_xor_sync(0xffffffffu, neq, o);
            if (neq > need_eq) {
                for (int j = lane; j < m; j += 32) {
                    if (eqKey[j] == bestKey) {
                        unsigned ij = eqIdx[j];
                        int lt = 0;
                        for (int q = 0; q < m; q++)
                            lt += (eqKey[q] == bestKey && eqIdx[q] < ij);
                        if (lt == need_eq - 1) cut = ij;
                    }
                }
                #pragma unroll
                for (int o = 16; o; o >>= 1)
                    cut = min(cut, __shfl_xor_sync(0xffffffffu, cut, o));
            }
            if (lane == 0) { s_kthKey = bestKey; s_cutIdx = cut; }
        }
        __syncthreads();

        const unsigned kth = s_kthKey;
        const unsigned cut = s_cutIdx;

        // scatter winners (all > T0 > 0, relu is identity)
        if (hasC && (myKey > kth || (myKey == kth && myIdx <= cut)))
            orow_f[myIdx] = __uint_as_float(myKey & 0x7fffffffu);

    } else {
        // ================= FALLBACK (exact, slow, ~never taken) =================
        for (int i = tid; i < NBINS_S; i += THREADS) hist[i] = 0;
        if (tid == 0) s_ncand = 0;
        __syncthreads();

        // histogram of top 11 key bits over full row
        #pragma unroll
        for (int i = 0; i < F4_PER_THREAD; i++) {
            float4 v = xr[tid + i * THREADS];
            float vals[4] = {v.x, v.y, v.z, v.w};
            #pragma unroll
            for (int c = 0; c < 4; c++)
                atomicAdd(&hist[fkey(vals[c]) >> 21], 1u);
        }
        __syncthreads();

        // 2-level descending scan to find threshold bin
        unsigned cnt4[4];
        unsigned mySum = 0;
        #pragma unroll
        for (int j = 0; j < 4; j++) {
            cnt4[j] = hist[NBINS_S - 1 - (wid * 128 + lane * 4 + j)];
            mySum += cnt4[j];
        }
        unsigned wtot = mySum;
        #pragma unroll
        for (int o = 16; o; o >>= 1) wtot += __shfl_xor_sync(0xffffffffu, wtot, o);
        if (lane == 0) chunkTot[wid] = wtot;
        __syncthreads();
        if (tid == 0) {
            unsigned acc = 0;
            for (int w = 0; w < NCHUNK; w++) { chunkPref[w] = acc; acc += chunkTot[w]; }
        }
        __syncthreads();
        {
            unsigned pref = chunkPref[wid];
            if (pref < K_TOP && pref + chunkTot[wid] >= K_TOP) {
                unsigned inc = mySum;
                #pragma unroll
                for (int o = 1; o < 32; o <<= 1) {
                    unsigned t = __shfl_up_sync(0xffffffffu, inc, o);
                    if (lane >= o) inc += t;
                }
                unsigned ball = __ballot_sync(0xffffffffu, pref + inc >= K_TOP);
                int sel = __ffs(ball) - 1;
                if (lane == sel) {
                    unsigned cum = pref + inc - mySum;
                    #pragma unroll
                    for (int j = 0; j < 4; j++) {
                        if (cum + cnt4[j] >= K_TOP) {
                            s_thrBin = (unsigned)(NBINS_S - 1 - (wid * 128 + lane * 4 + j));
                            s_nAbove = cum;
                            break;
                        }
                        cum += cnt4[j];
                    }
                }
            }
        }
        __syncthreads();
        const unsigned thrBin = s_thrBin;

        // collect candidates from threshold bin
        #pragma unroll
        for (int i = 0; i < F4_PER_THREAD; i++) {
            float4 v = xr[tid + i * THREADS];
            float vals[4] = {v.x, v.y, v.z, v.w};
            #pragma unroll
            for (int c = 0; c < 4; c++) {
                unsigned key = fkey(vals[c]);
                if ((key >> 21) == thrBin) {
                    unsigned p = atomicAdd(&s_ncand, 1u);
                    if (p < CAP) {
                        candKey[p] = key;
                        candIdx[p] = (unsigned)((tid + i * THREADS) * 4 + c);
                    }
                }
            }
        }
        __syncthreads();

        // warp 0: exact kth + tie cutoff
        if (tid < 32) {
            int ncf = (int)min(s_ncand, (unsigned)CAP);
            int need = K_TOP - (int)s_nAbove;

            unsigned bestKey = 0xffffffffu;
            for (int j = lane; j < ncf; j += 32) {
                unsigned kj = candKey[j];
                int gt = 0;
                for (int q = 0; q < ncf; q++) gt += (candKey[q] > kj);
                if (gt < need) bestKey = min(bestKey, kj);
            }
            #pragma unroll
            for (int o = 16; o; o >>= 1)
                bestKey = min(bestKey, __shfl_xor_sync(0xffffffffu, bestKey, o));

            int ngt = 0;
            for (int j = lane; j < ncf; j += 32) ngt += (candKey[j] > bestKey);
            #pragma unroll
            for (int o = 16; o; o >>= 1) ngt += __shfl_xor_sync(0xffffffffu, ngt, o);
            int need_eq = need - ngt;

            unsigned cut = 0xffffffffu;
            for (int j = lane; j < ncf; j += 32) {
                if (candKey[j] == bestKey) {
                    unsigned ij = candIdx[j];
                    int lt = 0;
                    for (int q = 0; q < ncf; q++)
                        lt += (candKey[q] == bestKey && candIdx[q] < ij);
                    if (lt == need_eq - 1) cut = ij;
                }
            }
            #pragma unroll
            for (int o = 16; o; o >>= 1)
                cut = min(cut, __shfl_xor_sync(0xffffffffu, cut, o));

            if (lane == 0) { s_kthKey = bestKey; s_cutIdx = cut; }
        }
        __syncthreads();

        const unsigned kth = s_kthKey;
        const unsigned cut = s_cutIdx;

        // re-read row (L2 hits), scatter winners with relu
        #pragma unroll
        for (int i = 0; i < F4_PER_THREAD; i++) {
            float4 v = xr[tid + i * THREADS];
            float vals[4] = {v.x, v.y, v.z, v.w};
            #pragma unroll
            for (int c = 0; c < 4; c++) {
                unsigned key = fkey(vals[c]);
                unsigned idx = (unsigned)((tid + i * THREADS) * 4 + c);
                if (key > kth || (key == kth && idx <= cut))
                    orow_f[idx] = fmaxf(vals[c], 0.0f);
            }
        }
    }
}

extern "C" void kernel_launch(void* const* d_in, const int* in_sizes, int n_in,
                              void* d_out, int out_size) {
    const float* x = (const float*)d_in[0];
    float* out = (float*)d_out;
    int rows = in_sizes[0] / N_COLS;   // 8192
    topk_act_kernel<<<rows, THREADS>>>(x, out);
}

// round 5
// speedup vs baseline: 4.9910x; 1.0708x over previous
#include <cuda_runtime.h>
#include <cstdint>

#define N_COLS 24576
#define K_TOP 64
#define THREADS 512
#define F4_PER_THREAD 12   // 24576 / 4 / 512
#define NBINS_F 4096       // pass-2 candidate histogram
#define NBINS_S 2048       // fallback full-row histogram
#define NCHUNK 16          // warps per CTA
#define CAP 512
#define T0 2.2f
#define MAX_ROWS 8192

// Scratch: packed candidates (key<<32 | idx) and per-row counts.
__device__ unsigned long long g_cand[(size_t)MAX_ROWS * CAP];
__device__ unsigned g_cnt[MAX_ROWS];

// Monotonic key: larger float -> larger unsigned key
__device__ __forceinline__ unsigned fkey(float x) {
    unsigned u = __float_as_uint(x);
    return (u & 0x80000000u) ? ~u : (u | 0x80000000u);
}

// ============================================================================
// Pass 1: pure stream. Read row, write zeros, emit candidates x > T0 to scratch.
// ============================================================================
__global__ __launch_bounds__(THREADS, 3)
void topk_pass1(const float* __restrict__ x, float* __restrict__ out) {
    __shared__ unsigned s_cnt;

    const int row = blockIdx.x;
    const float4* __restrict__ xr = (const float4*)(x + (size_t)row * N_COLS);
    float4* __restrict__ orow = (float4*)(out + (size_t)row * N_COLS);
    const int tid = threadIdx.x;

    if (tid == 0) s_cnt = 0;
    __syncthreads();

    unsigned long long* __restrict__ crow = g_cand + (size_t)row * CAP;

    #pragma unroll
    for (int i = 0; i < F4_PER_THREAD; i++) {
        float4 v = xr[tid + i * THREADS];
        orow[tid + i * THREADS] = make_float4(0.f, 0.f, 0.f, 0.f);
        float m01 = fmaxf(v.x, v.y), m23 = fmaxf(v.z, v.w);
        if (fmaxf(m01, m23) > T0) {
            float vals[4] = {v.x, v.y, v.z, v.w};
            #pragma unroll
            for (int c = 0; c < 4; c++) {
                if (vals[c] > T0) {
                    unsigned p = atomicAdd(&s_cnt, 1u);
                    if (p < CAP) {
                        unsigned idx = (unsigned)((tid + i * THREADS) * 4 + c);
                        crow[p] = ((unsigned long long)fkey(vals[c]) << 32) | idx;
                    }
                }
            }
        }
    }
    __syncthreads();
    if (tid == 0) g_cnt[row] = s_cnt;
}

// ============================================================================
// Pass 2: per-row selection over <=512 candidates (tiny traffic), scatter top-K.
// ============================================================================
__global__ __launch_bounds__(THREADS, 3)
void topk_pass2(const float* __restrict__ x, float* __restrict__ out) {
    __shared__ unsigned hist[NBINS_F];
    __shared__ unsigned chunkTot[NCHUNK], chunkPref[NCHUNK];
    __shared__ unsigned candKey[CAP], candIdx[CAP];
    __shared__ unsigned eqKey[CAP], eqIdx[CAP];
    __shared__ unsigned s_ncand, s_n2, s_maxKey, s_thrBin, s_nAbove, s_kthKey, s_cutIdx;

    const int row = blockIdx.x;
    float* __restrict__ orow_f = out + (size_t)row * N_COLS;
    const int tid = threadIdx.x;
    const int lane = tid & 31;
    const int wid = tid >> 5;

    for (int i = tid; i < NBINS_F; i += THREADS) hist[i] = 0;
    if (tid == 0) { s_ncand = 0; s_n2 = 0; s_maxKey = 0; }
    __syncthreads();

    const unsigned T0KEY = fkey(T0);
    const unsigned nc = g_cnt[row];

    if (nc >= K_TOP && nc <= CAP) {
        // ================= FAST PATH =================
        const bool hasC = (tid < (int)nc);
        unsigned myKey = 0u, myIdx = 0u;
        if (hasC) {
            unsigned long long pk = g_cand[(size_t)row * CAP + tid];
            myKey = (unsigned)(pk >> 32);
            myIdx = (unsigned)(pk & 0xffffffffu);
        }

        // block max of candidate keys
        unsigned wmax = myKey;
        #pragma unroll
        for (int o = 16; o; o >>= 1)
            wmax = max(wmax, __shfl_xor_sync(0xffffffffu, wmax, o));
        if (lane == 0) atomicMax(&s_maxKey, wmax);
        __syncthreads();

        // shift so (maxKey - T0KEY) >> shift fits in NBINS_F bins
        unsigned range = s_maxKey - T0KEY;
        int bits = 32 - __clz(range | 1u);
        int shift = bits > 12 ? bits - 12 : 0;
        const unsigned myBin = hasC ? ((myKey - T0KEY) >> shift) : 0u;

        if (hasC) atomicAdd(&hist[myBin], 1u);
        __syncthreads();

        // descending 2-level scan: thread t owns positions [8t, 8t+8)
        unsigned cnt8[8];
        unsigned mySum = 0;
        #pragma unroll
        for (int j = 0; j < 8; j++) {
            cnt8[j] = hist[NBINS_F - 1 - (tid * 8 + j)];
            mySum += cnt8[j];
        }
        unsigned wtot = mySum;
        #pragma unroll
        for (int o = 16; o; o >>= 1) wtot += __shfl_xor_sync(0xffffffffu, wtot, o);
        if (lane == 0) chunkTot[wid] = wtot;
        __syncthreads();
        if (tid == 0) {
            unsigned acc = 0;
            for (int w = 0; w < NCHUNK; w++) { chunkPref[w] = acc; acc += chunkTot[w]; }
        }
        __syncthreads();
        {
            unsigned pref = chunkPref[wid];
            if (pref < K_TOP && pref + chunkTot[wid] >= K_TOP) {
                unsigned inc = mySum;
                #pragma unroll
                for (int o = 1; o < 32; o <<= 1) {
                    unsigned t = __shfl_up_sync(0xffffffffu, inc, o);
                    if (lane >= o) inc += t;
                }
                unsigned ball = __ballot_sync(0xffffffffu, pref + inc >= K_TOP);
                int sel = __ffs(ball) - 1;
                if (lane == sel) {
                    unsigned cum = pref + inc - mySum;
                    #pragma unroll
                    for (int j = 0; j < 8; j++) {
                        if (cum + cnt8[j] >= K_TOP) {
                            s_thrBin = (unsigned)(NBINS_F - 1 - (tid * 8 + j));
                            s_nAbove = cum;
                            break;
                        }
                        cum += cnt8[j];
                    }
                }
            }
        }
        __syncthreads();

        // gather candidates in the threshold bin (typically 1-3)
        if (hasC && myBin == s_thrBin) {
            unsigned p = atomicAdd(&s_n2, 1u);
            eqKey[p] = myKey;
            eqIdx[p] = myIdx;
        }
        __syncthreads();

        // warp 0: exact kth + tie index cutoff among the in-bin set
        if (tid < 32) {
            int m = (int)s_n2;
            int need = K_TOP - (int)s_nAbove;   // >= 1

            unsigned bestKey = 0xffffffffu;
            for (int j = lane; j < m; j += 32) {
                unsigned kj = eqKey[j];
                int gt = 0;
                for (int q = 0; q < m; q++) gt += (eqKey[q] > kj);
                if (gt < need) bestKey = min(bestKey, kj);
            }
            #pragma unroll
            for (int o = 16; o; o >>= 1)
                bestKey = min(bestKey, __shfl_xor_sync(0xffffffffu, bestKey, o));

            int ngt = 0;
            for (int j = lane; j < m; j += 32) ngt += (eqKey[j] > bestKey);
            #pragma unroll
            for (int o = 16; o; o >>= 1) ngt += __shfl_xor_sync(0xffffffffu, ngt, o);
            int need_eq = need - ngt;           // >= 1

            unsigned cut = 0xffffffffu;
            int neq = 0;
            for (int j = lane; j < m; j += 32) neq += (eqKey[j] == bestKey);
            #pragma unroll
            for (int o = 16; o; o >>= 1) neq += __shfl_xor_sync(0xffffffffu, neq, o);
            if (neq > need_eq) {
                for (int j = lane; j < m; j += 32) {
                    if (eqKey[j] == bestKey) {
                        unsigned ij = eqIdx[j];
                        int lt = 0;
                        for (int q = 0; q < m; q++)
                            lt += (eqKey[q] == bestKey && eqIdx[q] < ij);
                        if (lt == need_eq - 1) cut = ij;
                    }
                }
                #pragma unroll
                for (int o = 16; o; o >>= 1)
                    cut = min(cut, __shfl_xor_sync(0xffffffffu, cut, o));
            }
            if (lane == 0) { s_kthKey = bestKey; s_cutIdx = cut; }
        }
        __syncthreads();

        const unsigned kth = s_kthKey;
        const unsigned cut = s_cutIdx;

        // scatter winners (all > T0 > 0, relu is identity)
        if (hasC && (myKey > kth || (myKey == kth && myIdx <= cut)))
            orow_f[myIdx] = __uint_as_float(myKey & 0x7fffffffu);

    } else {
        // ================= FALLBACK (exact, slow, ~never taken) =================
        const float4* __restrict__ xr = (const float4*)(x + (size_t)row * N_COLS);

        for (int i = tid; i < NBINS_S; i += THREADS) hist[i] = 0;
        if (tid == 0) s_ncand = 0;
        __syncthreads();

        // histogram of top 11 key bits over full row
        #pragma unroll
        for (int i = 0; i < F4_PER_THREAD; i++) {
            float4 v = xr[tid + i * THREADS];
            float vals[4] = {v.x, v.y, v.z, v.w};
            #pragma unroll
            for (int c = 0; c < 4; c++)
                atomicAdd(&hist[fkey(vals[c]) >> 21], 1u);
        }
        __syncthreads();

        // 2-level descending scan to find threshold bin
        unsigned cnt4[4];
        unsigned mySum = 0;
        #pragma unroll
        for (int j = 0; j < 4; j++) {
            cnt4[j] = hist[NBINS_S - 1 - (wid * 128 + lane * 4 + j)];
            mySum += cnt4[j];
        }
        unsigned wtot = mySum;
        #pragma unroll
        for (int o = 16; o; o >>= 1) wtot += __shfl_xor_sync(0xffffffffu, wtot, o);
        if (lane == 0) chunkTot[wid] = wtot;
        __syncthreads();
        if (tid == 0) {
            unsigned acc = 0;
            for (int w = 0; w < NCHUNK; w++) { chunkPref[w] = acc; acc += chunkTot[w]; }
        }
        __syncthreads();
        {
            unsigned pref = chunkPref[wid];
            if (pref < K_TOP && pref + chunkTot[wid] >= K_TOP) {
                unsigned inc = mySum;
                #pragma unroll
                for (int o = 1; o < 32; o <<= 1) {
                    unsigned t = __shfl_up_sync(0xffffffffu, inc, o);
                    if (lane >= o) inc += t;
                }
                unsigned ball = __ballot_sync(0xffffffffu, pref + inc >= K_TOP);
                int sel = __ffs(ball) - 1;
                if (lane == sel) {
                    unsigned cum = pref + inc - mySum;
                    #pragma unroll
                    for (int j = 0; j < 4; j++) {
                        if (cum + cnt4[j] >= K_TOP) {
                            s_thrBin = (unsigned)(NBINS_S - 1 - (wid * 128 + lane * 4 + j));
                            s_nAbove = cum;
                            break;
                        }
                        cum += cnt4[j];
                    }
                }
            }
        }
        __syncthreads();
        const unsigned thrBin = s_thrBin;

        // collect candidates from threshold bin
        #pragma unroll
        for (int i = 0; i < F4_PER_THREAD; i++) {
            float4 v = xr[tid + i * THREADS];
            float vals[4] = {v.x, v.y, v.z, v.w};
            #pragma unroll
            for (int c = 0; c < 4; c++) {
                unsigned key = fkey(vals[c]);
                if ((key >> 21) == thrBin) {
                    unsigned p = atomicAdd(&s_ncand, 1u);
                    if (p < CAP) {
                        candKey[p] = key;
                        candIdx[p] = (unsigned)((tid + i * THREADS) * 4 + c);
                    }
                }
            }
        }
        __syncthreads();

        // warp 0: exact kth + tie cutoff
        if (tid < 32) {
            int ncf = (int)min(s_ncand, (unsigned)CAP);
            int need = K_TOP - (int)s_nAbove;

            unsigned bestKey = 0xffffffffu;
            for (int j = lane; j < ncf; j += 32) {
                unsigned kj = candKey[j];
                int gt = 0;
                for (int q = 0; q < ncf; q++) gt += (candKey[q] > kj);
                if (gt < need) bestKey = min(bestKey, kj);
            }
            #pragma unroll
            for (int o = 16; o; o >>= 1)
                bestKey = min(bestKey, __shfl_xor_sync(0xffffffffu, bestKey, o));

            int ngt = 0;
            for (int j = lane; j < ncf; j += 32) ngt += (candKey[j] > bestKey);
            #pragma unroll
            for (int o = 16; o; o >>= 1) ngt += __shfl_xor_sync(0xffffffffu, ngt, o);
            int need_eq = need - ngt;

            unsigned cut = 0xffffffffu;
            for (int j = lane; j < ncf; j += 32) {
                if (candKey[j] == bestKey) {
                    unsigned ij = candIdx[j];
                    int lt = 0;
                    for (int q = 0; q < ncf; q++)
                        lt += (candKey[q] == bestKey && candIdx[q] < ij);
                    if (lt == need_eq - 1) cut = ij;
                }
            }
            #pragma unroll
            for (int o = 16; o; o >>= 1)
                cut = min(cut, __shfl_xor_sync(0xffffffffu, cut, o));

            if (lane == 0) { s_kthKey = bestKey; s_cutIdx = cut; }
        }
        __syncthreads();

        const unsigned kth = s_kthKey;
        const unsigned cut = s_cutIdx;

        // re-read row (L2 hits), scatter winners with relu
        #pragma unroll
        for (int i = 0; i < F4_PER_THREAD; i++) {
            float4 v = xr[tid + i * THREADS];
            float vals[4] = {v.x, v.y, v.z, v.w};
            #pragma unroll
            for (int c = 0; c < 4; c++) {
                unsigned key = fkey(vals[c]);
                unsigned idx = (unsigned)((tid + i * THREADS) * 4 + c);
                if (key > kth || (key == kth && idx <= cut))
                    orow_f[idx] = fmaxf(vals[c], 0.0f);
            }
        }
    }
}

extern "C" void kernel_launch(void* const* d_in, const int* in_sizes, int n_in,
                              void* d_out, int out_size) {
    const float* x = (const float*)d_in[0];
    float* out = (float*)d_out;
    int rows = in_sizes[0] / N_COLS;   // 8192
    topk_pass1<<<rows, THREADS>>>(x, out);
    topk_pass2<<<rows, THREADS>>>(x, out);
}

// round 6
// speedup vs baseline: 5.7851x; 1.1591x over previous
#include <cuda_runtime.h>
#include <cstdint>

#define N_COLS 24576
#define K_TOP 64
#define THREADS 512
#define F4_PER_THREAD 12   // 24576 / 4 / 512
#define CAP 1024           // scratch candidates per row
#define CPL 32             // candidates per lane (CAP/32)
#define ROWS_PER_CTA 16
#define T0 2.2f
#define MAX_ROWS 8192

// Scratch: packed candidates (key<<32 | idx) and per-row counts.
__device__ unsigned long long g_cand[(size_t)MAX_ROWS * CAP];
__device__ unsigned g_cnt[MAX_ROWS];

// Monotonic key: larger float -> larger unsigned key
__device__ __forceinline__ unsigned fkey(float x) {
    unsigned u = __float_as_uint(x);
    return (u & 0x80000000u) ? ~u : (u | 0x80000000u);
}

// ============================================================================
// Pass 1: pure stream. Read row, write zeros, emit candidates x > T0 to scratch.
// ============================================================================
__global__ __launch_bounds__(THREADS, 3)
void topk_pass1(const float* __restrict__ x, float* __restrict__ out) {
    __shared__ unsigned s_cnt;

    const int row = blockIdx.x;
    const float4* __restrict__ xr = (const float4*)(x + (size_t)row * N_COLS);
    float4* __restrict__ orow = (float4*)(out + (size_t)row * N_COLS);
    const int tid = threadIdx.x;

    if (tid == 0) s_cnt = 0;
    __syncthreads();

    unsigned long long* __restrict__ crow = g_cand + (size_t)row * CAP;

    #pragma unroll
    for (int i = 0; i < F4_PER_THREAD; i++) {
        float4 v = xr[tid + i * THREADS];
        orow[tid + i * THREADS] = make_float4(0.f, 0.f, 0.f, 0.f);
        float m01 = fmaxf(v.x, v.y), m23 = fmaxf(v.z, v.w);
        if (fmaxf(m01, m23) > T0) {
            float vals[4] = {v.x, v.y, v.z, v.w};
            #pragma unroll
            for (int c = 0; c < 4; c++) {
                if (vals[c] > T0) {
                    unsigned p = atomicAdd(&s_cnt, 1u);
                    if (p < CAP) {
                        unsigned idx = (unsigned)((tid + i * THREADS) * 4 + c);
                        crow[p] = ((unsigned long long)fkey(vals[c]) << 32) | idx;
                    }
                }
            }
        }
    }
    __syncthreads();
    if (tid == 0) g_cnt[row] = s_cnt;
}

// ============================================================================
// Pass 2: warp-per-row selection, barrier-free. 16 rows per CTA.
// ============================================================================
__global__ __launch_bounds__(THREADS, 2)
void topk_pass2(const float* __restrict__ x, float* __restrict__ out) {
    const int lane = threadIdx.x & 31;
    const int warp = threadIdx.x >> 5;
    const int row = blockIdx.x * ROWS_PER_CTA + warp;

    float* __restrict__ orow = out + (size_t)row * N_COLS;
    const unsigned long long* __restrict__ crow = g_cand + (size_t)row * CAP;
    const unsigned nc = g_cnt[row];
    const unsigned T0KEY = fkey(T0);

    if (nc >= K_TOP && nc <= CAP) {
        // ================= FAST PATH (warp-local, no barriers) =================
        const int nslot = (int)((nc + 31) >> 5);

        unsigned key[CPL];
        #pragma unroll
        for (int j = 0; j < CPL; j++) {
            unsigned pos = (unsigned)lane + j * 32u;
            key[j] = (pos < nc) ? (unsigned)(crow[pos] >> 32) : 0u;
        }

        // warp max key -> search upper bound
        unsigned wmax = 0;
        #pragma unroll
        for (int j = 0; j < CPL; j++) wmax = max(wmax, key[j]);
        wmax = __reduce_max_sync(0xffffffffu, wmax);

        // binary search: smallest T with count(key > T) < K  ==> T = kth key
        unsigned lo = T0KEY, hi = wmax;
        while (lo < hi) {
            unsigned mid = lo + ((hi - lo) >> 1);
            unsigned c = 0;
            #pragma unroll
            for (int j = 0; j < CPL; j++) c += (key[j] > mid) ? 1u : 0u;
            c = __reduce_add_sync(0xffffffffu, c);
            if (c < K_TOP) hi = mid; else lo = mid + 1;
        }
        const unsigned kth = lo;

        unsigned cgt = 0, ceq = 0;
        #pragma unroll
        for (int j = 0; j < CPL; j++) {
            cgt += (key[j] > kth) ? 1u : 0u;
            ceq += (key[j] == kth) ? 1u : 0u;
        }
        cgt = __reduce_add_sync(0xffffffffu, cgt);
        ceq = __reduce_add_sync(0xffffffffu, ceq);
        const int needEq = K_TOP - (int)cgt;   // >= 1

        unsigned cut = 0xffffffffu;            // default: take all ties
        if ((int)ceq > needEq) {
            // keep the needEq smallest indices among ties (jax tie-break)
            unsigned l2 = 0, h2 = N_COLS - 1;
            while (l2 < h2) {
                unsigned m2 = l2 + ((h2 - l2) >> 1);
                unsigned c2 = 0;
                for (int j = 0; j < nslot; j++) {
                    unsigned pos = (unsigned)lane + j * 32u;
                    if (pos < nc) {
                        unsigned long long pk = crow[pos];
                        if ((unsigned)(pk >> 32) == kth && (unsigned)pk <= m2) c2++;
                    }
                }
                c2 = __reduce_add_sync(0xffffffffu, c2);
                if (c2 >= (unsigned)needEq) h2 = m2; else l2 = m2 + 1;
            }
            cut = l2;
        }

        // scatter winners (all > T0 > 0, relu is identity)
        for (int j = 0; j < nslot; j++) {
            unsigned pos = (unsigned)lane + j * 32u;
            if (pos < nc) {
                unsigned long long pk = crow[pos];
                unsigned k = (unsigned)(pk >> 32);
                unsigned id = (unsigned)pk;
                if (k > kth || (k == kth && id <= cut))
                    orow[id] = __uint_as_float(k & 0x7fffffffu);
            }
        }
    } else {
        // ====== FALLBACK: exact warp-level full-row select (~never taken) ======
        const float4* __restrict__ xr = (const float4*)(x + (size_t)row * N_COLS);
        const int NF4 = N_COLS / 4;

        unsigned lo = 0u, hi = 0xffffffffu;
        while (lo < hi) {
            unsigned mid = lo + ((hi - lo) >> 1);
            unsigned c = 0;
            for (int p = lane; p < NF4; p += 32) {
                float4 v = xr[p];
                c += (fkey(v.x) > mid) ? 1u : 0u;
                c += (fkey(v.y) > mid) ? 1u : 0u;
                c += (fkey(v.z) > mid) ? 1u : 0u;
                c += (fkey(v.w) > mid) ? 1u : 0u;
            }
            c = __reduce_add_sync(0xffffffffu, c);
            if (c < K_TOP) hi = mid; else lo = mid + 1;
        }
        const unsigned kth = lo;

        unsigned cgt = 0, ceq = 0;
        for (int p = lane; p < NF4; p += 32) {
            float4 v = xr[p];
            float vals[4] = {v.x, v.y, v.z, v.w};
            #pragma unroll
            for (int c4 = 0; c4 < 4; c4++) {
                unsigned k = fkey(vals[c4]);
                cgt += (k > kth) ? 1u : 0u;
                ceq += (k == kth) ? 1u : 0u;
            }
        }
        cgt = __reduce_add_sync(0xffffffffu, cgt);
        ceq = __reduce_add_sync(0xffffffffu, ceq);
        const int needEq = K_TOP - (int)cgt;

        unsigned cut = 0xffffffffu;
        if ((int)ceq > needEq) {
            unsigned l2 = 0, h2 = N_COLS - 1;
            while (l2 < h2) {
                unsigned m2 = l2 + ((h2 - l2) >> 1);
                unsigned c2 = 0;
                for (int p = lane; p < NF4; p += 32) {
                    float4 v = xr[p];
                    float vals[4] = {v.x, v.y, v.z, v.w};
                    #pragma unroll
                    for (int c4 = 0; c4 < 4; c4++) {
                        unsigned k = fkey(vals[c4]);
                        unsigned id = (unsigned)(p * 4 + c4);
                        if (k == kth && id <= m2) c2++;
                    }
                }
                c2 = __reduce_add_sync(0xffffffffu, c2);
                if (c2 >= (unsigned)needEq) h2 = m2; else l2 = m2 + 1;
            }
            cut = l2;
        }

        // scatter with relu (out already zeroed by pass 1)
        for (int p = lane; p < NF4; p += 32) {
            float4 v = xr[p];
            float vals[4] = {v.x, v.y, v.z, v.w};
            #pragma unroll
            for (int c4 = 0; c4 < 4; c4++) {
                unsigned k = fkey(vals[c4]);
                unsigned id = (unsigned)(p * 4 + c4);
                if (k > kth || (k == kth && id <= cut))
                    orow[id] = fmaxf(vals[c4], 0.0f);
            }
        }
    }
}

extern "C" void kernel_launch(void* const* d_in, const int* in_sizes, int n_in,
                              void* d_out, int out_size) {
    const float* x = (const float*)d_in[0];
    float* out = (float*)d_out;
    int rows = in_sizes[0] / N_COLS;   // 8192
    topk_pass1<<<rows, THREADS>>>(x, out);
    topk_pass2<<<rows / ROWS_PER_CTA, THREADS>>>(x, out);
}

// round 7
// speedup vs baseline: 6.2839x; 1.0862x over previous
#include <cuda_runtime.h>
#include <cstdint>

#define N_COLS 24576
#define K_TOP 64
#define THREADS 512
#define F4_PER_THREAD 12   // 24576 / 4 / 512
#define CAP 512            // scratch candidates per row (mean 341, sd ~18; +9.3 sigma)
#define CPL 16             // candidates per lane (CAP/32)
#define ROWS_PER_CTA 16
#define T0 2.2f
#define MAX_ROWS 8192

// Scratch: packed candidates (key<<32 | idx) and per-row counts.
__device__ unsigned long long g_cand[(size_t)MAX_ROWS * CAP];
__device__ unsigned g_cnt[MAX_ROWS];

// Monotonic key: larger float -> larger unsigned key
__device__ __forceinline__ unsigned fkey(float x) {
    unsigned u = __float_as_uint(x);
    return (u & 0x80000000u) ? ~u : (u | 0x80000000u);
}

// ============================================================================
// Pass 1: pure stream. Read row, write zeros, emit candidates x > T0 to scratch.
// Loads front-batched in groups of 4 to keep the L1tex queue deep.
// ============================================================================
__global__ __launch_bounds__(THREADS, 3)
void topk_pass1(const float* __restrict__ x, float* __restrict__ out) {
    __shared__ unsigned s_cnt;

    const int row = blockIdx.x;
    const float4* __restrict__ xr = (const float4*)(x + (size_t)row * N_COLS);
    float4* __restrict__ orow = (float4*)(out + (size_t)row * N_COLS);
    const int tid = threadIdx.x;

    if (tid == 0) s_cnt = 0;
    __syncthreads();

    unsigned long long* __restrict__ crow = g_cand + (size_t)row * CAP;
    const float4 zero4 = make_float4(0.f, 0.f, 0.f, 0.f);

    #pragma unroll
    for (int g = 0; g < F4_PER_THREAD / 4; g++) {
        float4 v[4];
        #pragma unroll
        for (int j = 0; j < 4; j++)
            v[j] = xr[tid + (g * 4 + j) * THREADS];

        #pragma unroll
        for (int j = 0; j < 4; j++)
            __stcs(&orow[tid + (g * 4 + j) * THREADS], zero4);

        #pragma unroll
        for (int j = 0; j < 4; j++) {
            float m01 = fmaxf(v[j].x, v[j].y), m23 = fmaxf(v[j].z, v[j].w);
            if (fmaxf(m01, m23) > T0) {
                float vals[4] = {v[j].x, v[j].y, v[j].z, v[j].w};
                #pragma unroll
                for (int c = 0; c < 4; c++) {
                    if (vals[c] > T0) {
                        unsigned p = atomicAdd(&s_cnt, 1u);
                        if (p < CAP) {
                            unsigned idx = (unsigned)((tid + (g * 4 + j) * THREADS) * 4 + c);
                            crow[p] = ((unsigned long long)fkey(vals[c]) << 32) | idx;
                        }
                    }
                }
            }
        }
    }
    __syncthreads();
    if (tid == 0) g_cnt[row] = s_cnt;
}

// ============================================================================
// Pass 2: warp-per-row selection, barrier-free. 16 rows per CTA.
// ============================================================================
__global__ __launch_bounds__(THREADS, 3)
void topk_pass2(const float* __restrict__ x, float* __restrict__ out) {
    const int lane = threadIdx.x & 31;
    const int warp = threadIdx.x >> 5;
    const int row = blockIdx.x * ROWS_PER_CTA + warp;

    float* __restrict__ orow = out + (size_t)row * N_COLS;
    const unsigned long long* __restrict__ crow = g_cand + (size_t)row * CAP;
    const unsigned nc = g_cnt[row];
    const unsigned T0KEY = fkey(T0);

    if (nc >= K_TOP && nc <= CAP) {
        // ================= FAST PATH (warp-local, no barriers) =================
        const int nslot = (int)((nc + 31) >> 5);

        unsigned key[CPL];
        #pragma unroll
        for (int j = 0; j < CPL; j++) {
            unsigned pos = (unsigned)lane + j * 32u;
            key[j] = (pos < nc) ? (unsigned)(crow[pos] >> 32) : 0u;
        }

        // warp max key -> search upper bound
        unsigned wmax = 0;
        #pragma unroll
        for (int j = 0; j < CPL; j++) wmax = max(wmax, key[j]);
        wmax = __reduce_max_sync(0xffffffffu, wmax);

        // binary search: smallest T with count(key > T) < K  ==> T = kth key
        unsigned lo = T0KEY, hi = wmax;
        while (lo < hi) {
            unsigned mid = lo + ((hi - lo) >> 1);
            unsigned c = 0;
            #pragma unroll
            for (int j = 0; j < CPL; j++) c += (key[j] > mid) ? 1u : 0u;
            c = __reduce_add_sync(0xffffffffu, c);
            if (c < K_TOP) hi = mid; else lo = mid + 1;
        }
        const unsigned kth = lo;

        unsigned cgt = 0, ceq = 0;
        #pragma unroll
        for (int j = 0; j < CPL; j++) {
            cgt += (key[j] > kth) ? 1u : 0u;
            ceq += (key[j] == kth) ? 1u : 0u;
        }
        cgt = __reduce_add_sync(0xffffffffu, cgt);
        ceq = __reduce_add_sync(0xffffffffu, ceq);
        const int needEq = K_TOP - (int)cgt;   // >= 1

        unsigned cut = 0xffffffffu;            // default: take all ties
        if ((int)ceq > needEq) {
            // keep the needEq smallest indices among ties (jax tie-break)
            unsigned l2 = 0, h2 = N_COLS - 1;
            while (l2 < h2) {
                unsigned m2 = l2 + ((h2 - l2) >> 1);
                unsigned c2 = 0;
                for (int j = 0; j < nslot; j++) {
                    unsigned pos = (unsigned)lane + j * 32u;
                    if (pos < nc) {
                        unsigned long long pk = crow[pos];
                        if ((unsigned)(pk >> 32) == kth && (unsigned)pk <= m2) c2++;
                    }
                }
                c2 = __reduce_add_sync(0xffffffffu, c2);
                if (c2 >= (unsigned)needEq) h2 = m2; else l2 = m2 + 1;
            }
            cut = l2;
        }

        // scatter winners (all > T0 > 0, relu is identity)
        for (int j = 0; j < nslot; j++) {
            unsigned pos = (unsigned)lane + j * 32u;
            if (pos < nc) {
                unsigned long long pk = crow[pos];
                unsigned k = (unsigned)(pk >> 32);
                unsigned id = (unsigned)pk;
                if (k > kth || (k == kth && id <= cut))
                    orow[id] = __uint_as_float(k & 0x7fffffffu);
            }
        }
    } else {
        // ====== FALLBACK: exact warp-level full-row select (~never taken) ======
        const float4* __restrict__ xr = (const float4*)(x + (size_t)row * N_COLS);
        const int NF4 = N_COLS / 4;

        unsigned lo = 0u, hi = 0xffffffffu;
        while (lo < hi) {
            unsigned mid = lo + ((hi - lo) >> 1);
            unsigned c = 0;
            for (int p = lane; p < NF4; p += 32) {
                float4 v = xr[p];
                c += (fkey(v.x) > mid) ? 1u : 0u;
                c += (fkey(v.y) > mid) ? 1u : 0u;
                c += (fkey(v.z) > mid) ? 1u : 0u;
                c += (fkey(v.w) > mid) ? 1u : 0u;
            }
            c = __reduce_add_sync(0xffffffffu, c);
            if (c < K_TOP) hi = mid; else lo = mid + 1;
        }
        const unsigned kth = lo;

        unsigned cgt = 0, ceq = 0;
        for (int p = lane; p < NF4; p += 32) {
            float4 v = xr[p];
            float vals[4] = {v.x, v.y, v.z, v.w};
            #pragma unroll
            for (int c4 = 0; c4 < 4; c4++) {
                unsigned k = fkey(vals[c4]);
                cgt += (k > kth) ? 1u : 0u;
                ceq += (k == kth) ? 1u : 0u;
            }
        }
        cgt = __reduce_add_sync(0xffffffffu, cgt);
        ceq = __reduce_add_sync(0xffffffffu, ceq);
        const int needEq = K_TOP - (int)cgt;

        unsigned cut = 0xffffffffu;
        if ((int)ceq > needEq) {
            unsigned l2 = 0, h2 = N_COLS - 1;
            while (l2 < h2) {
                unsigned m2 = l2 + ((h2 - l2) >> 1);
                unsigned c2 = 0;
                for (int p = lane; p < NF4; p += 32) {
                    float4 v = xr[p];
                    float vals[4] = {v.x, v.y, v.z, v.w};
                    #pragma unroll
                    for (int c4 = 0; c4 < 4; c4++) {
                        unsigned k = fkey(vals[c4]);
                        unsigned id = (unsigned)(p * 4 + c4);
                        if (k == kth && id <= m2) c2++;
                    }
                }
                c2 = __reduce_add_sync(0xffffffffu, c2);
                if (c2 >= (unsigned)needEq) h2 = m2; else l2 = m2 + 1;
            }
            cut = l2;
        }

        // scatter with relu (out already zeroed by pass 1)
        for (int p = lane; p < NF4; p += 32) {
            float4 v = xr[p];
            float vals[4] = {v.x, v.y, v.z, v.w};
            #pragma unroll
            for (int c4 = 0; c4 < 4; c4++) {
                unsigned k = fkey(vals[c4]);
                unsigned id = (unsigned)(p * 4 + c4);
                if (k > kth || (k == kth && id <= cut))
                    orow[id] = fmaxf(vals[c4], 0.0f);
            }
        }
    }
}

extern "C" void kernel_launch(void* const* d_in, const int* in_sizes, int n_in,
                              void* d_out, int out_size) {
    const float* x = (const float*)d_in[0];
    float* out = (float*)d_out;
    int rows = in_sizes[0] / N_COLS;   // 8192
    topk_pass1<<<rows, THREADS>>>(x, out);
    topk_pass2<<<rows / ROWS_PER_CTA, THREADS>>>(x, out);
}

// round 8
// speedup vs baseline: 6.7573x; 1.0753x over previous
#include <cuda_runtime.h>
#include <cstdint>

#define N_COLS 24576
#define K_TOP 64
#define THREADS 512
#define F4_PER_THREAD 12   // 24576 / 4 / 512
#define CAP 512            // candidates per row (mean 341, sd ~18; +9.3 sigma)
#define CPL 16             // candidates per lane (CAP/32)
#define T0 2.2f

// Monotonic key: larger float -> larger unsigned key
__device__ __forceinline__ unsigned fkey(float x) {
    unsigned u = __float_as_uint(x);
    return (u & 0x80000000u) ? ~u : (u | 0x80000000u);
}

__global__ __launch_bounds__(THREADS, 3)
void topk_fused(const float* __restrict__ x, float* __restrict__ out) {
    __shared__ unsigned sKey[CAP];
    __shared__ unsigned sIdx[CAP];
    __shared__ unsigned s_cnt;

    const int row = blockIdx.x;
    const float4* __restrict__ xr = (const float4*)(x + (size_t)row * N_COLS);
    float4* __restrict__ orow4 = (float4*)(out + (size_t)row * N_COLS);
    float* __restrict__ orow = out + (size_t)row * N_COLS;
    const int tid = threadIdx.x;
    const int lane = tid & 31;

    if (tid == 0) s_cnt = 0;
    __syncthreads();

    const float4 zero4 = make_float4(0.f, 0.f, 0.f, 0.f);

    // ---- Phase 1: stream row, write zeros, collect candidates x > T0 to smem ----
    #pragma unroll
    for (int g = 0; g < F4_PER_THREAD / 4; g++) {
        float4 v[4];
        #pragma unroll
        for (int j = 0; j < 4; j++)
            v[j] = xr[tid + (g * 4 + j) * THREADS];

        #pragma unroll
        for (int j = 0; j < 4; j++)
            __stcs(&orow4[tid + (g * 4 + j) * THREADS], zero4);

        #pragma unroll
        for (int j = 0; j < 4; j++) {
            float m01 = fmaxf(v[j].x, v[j].y), m23 = fmaxf(v[j].z, v[j].w);
            if (fmaxf(m01, m23) > T0) {
                float vals[4] = {v[j].x, v[j].y, v[j].z, v[j].w};
                #pragma unroll
                for (int c = 0; c < 4; c++) {
                    if (vals[c] > T0) {
                        unsigned p = atomicAdd(&s_cnt, 1u);
                        if (p < CAP) {
                            sKey[p] = fkey(vals[c]);
                            sIdx[p] = (unsigned)((tid + (g * 4 + j) * THREADS) * 4 + c);
                        }
                    }
                }
            }
        }
    }
    __syncthreads();

    // ---- Phase 2: warp 0 selects + scatters; other warps retire ----
    if (tid >= 32) return;

    const unsigned nc = s_cnt;
    const unsigned T0KEY = fkey(T0);

    if (nc >= K_TOP && nc <= CAP) {
        // ============ FAST PATH (warp-local, barrier-free) ============
        const int nslot = (int)((nc + 31) >> 5);

        unsigned key[CPL];
        #pragma unroll
        for (int j = 0; j < CPL; j++) {
            unsigned pos = (unsigned)lane + j * 32u;
            key[j] = (pos < nc) ? sKey[pos] : 0u;
        }

        // warp max key -> search upper bound
        unsigned wmax = 0;
        #pragma unroll
        for (int j = 0; j < CPL; j++) wmax = max(wmax, key[j]);
        wmax = __reduce_max_sync(0xffffffffu, wmax);

        // binary search: smallest T with count(key > T) < K  ==> T = kth key
        unsigned lo = T0KEY, hi = wmax;
        while (lo < hi) {
            unsigned mid = lo + ((hi - lo) >> 1);
            unsigned c = 0;
            #pragma unroll
            for (int j = 0; j < CPL; j++) c += (key[j] > mid) ? 1u : 0u;
            c = __reduce_add_sync(0xffffffffu, c);
            if (c < K_TOP) hi = mid; else lo = mid + 1;
        }
        const unsigned kth = lo;

        unsigned cgt = 0, ceq = 0;
        #pragma unroll
        for (int j = 0; j < CPL; j++) {
            cgt += (key[j] > kth) ? 1u : 0u;
            ceq += (key[j] == kth) ? 1u : 0u;
        }
        cgt = __reduce_add_sync(0xffffffffu, cgt);
        ceq = __reduce_add_sync(0xffffffffu, ceq);
        const int needEq = K_TOP - (int)cgt;   // >= 1

        unsigned cut = 0xffffffffu;            // default: take all ties
        if ((int)ceq > needEq) {
            // keep the needEq smallest indices among ties (jax tie-break)
            unsigned l2 = 0, h2 = N_COLS - 1;
            while (l2 < h2) {
                unsigned m2 = l2 + ((h2 - l2) >> 1);
                unsigned c2 = 0;
                for (int j = 0; j < nslot; j++) {
                    unsigned pos = (unsigned)lane + j * 32u;
                    if (pos < nc && sKey[pos] == kth && sIdx[pos] <= m2) c2++;
                }
                c2 = __reduce_add_sync(0xffffffffu, c2);
                if (c2 >= (unsigned)needEq) h2 = m2; else l2 = m2 + 1;
            }
            cut = l2;
        }

        // scatter winners (all > T0 > 0, relu is identity)
        for (int j = 0; j < nslot; j++) {
            unsigned pos = (unsigned)lane + j * 32u;
            if (pos < nc) {
                unsigned k = sKey[pos];
                unsigned id = sIdx[pos];
                if (k > kth || (k == kth && id <= cut))
                    orow[id] = __uint_as_float(k & 0x7fffffffu);
            }
        }
    } else {
        // ====== FALLBACK: exact warp-level full-row select (~never taken) ======
        const int NF4 = N_COLS / 4;

        unsigned lo = 0u, hi = 0xffffffffu;
        while (lo < hi) {
            unsigned mid = lo + ((hi - lo) >> 1);
            unsigned c = 0;
            for (int p = lane; p < NF4; p += 32) {
                float4 v = xr[p];
                c += (fkey(v.x) > mid) ? 1u : 0u;
                c += (fkey(v.y) > mid) ? 1u : 0u;
                c += (fkey(v.z) > mid) ? 1u : 0u;
                c += (fkey(v.w) > mid) ? 1u : 0u;
            }
            c = __reduce_add_sync(0xffffffffu, c);
            if (c < K_TOP) hi = mid; else lo = mid + 1;
        }
        const unsigned kth = lo;

        unsigned cgt = 0, ceq = 0;
        for (int p = lane; p < NF4; p += 32) {
            float4 v = xr[p];
            float vals[4] = {v.x, v.y, v.z, v.w};
            #pragma unroll
            for (int c4 = 0; c4 < 4; c4++) {
                unsigned k = fkey(vals[c4]);
                cgt += (k > kth) ? 1u : 0u;
                ceq += (k == kth) ? 1u : 0u;
            }
        }
        cgt = __reduce_add_sync(0xffffffffu, cgt);
        ceq = __reduce_add_sync(0xffffffffu, ceq);
        const int needEq = K_TOP - (int)cgt;

        unsigned cut = 0xffffffffu;
        if ((int)ceq > needEq) {
            unsigned l2 = 0, h2 = N_COLS - 1;
            while (l2 < h2) {
                unsigned m2 = l2 + ((h2 - l2) >> 1);
                unsigned c2 = 0;
                for (int p = lane; p < NF4; p += 32) {
                    float4 v = xr[p];
                    float vals[4] = {v.x, v.y, v.z, v.w};
                    #pragma unroll
                    for (int c4 = 0; c4 < 4; c4++) {
                        unsigned k = fkey(vals[c4]);
                        unsigned id = (unsigned)(p * 4 + c4);
                        if (k == kth && id <= m2) c2++;
                    }
                }
                c2 = __reduce_add_sync(0xffffffffu, c2);
                if (c2 >= (unsigned)needEq) h2 = m2; else l2 = m2 + 1;
            }
            cut = l2;
        }

        // scatter with relu (out already zeroed in phase 1)
        for (int p = lane; p < NF4; p += 32) {
            float4 v = xr[p];
            float vals[4] = {v.x, v.y, v.z, v.w};
            #pragma unroll
            for (int c4 = 0; c4 < 4; c4++) {
                unsigned k = fkey(vals[c4]);
                unsigned id = (unsigned)(p * 4 + c4);
                if (k > kth || (k == kth && id <= cut))
                    orow[id] = fmaxf(vals[c4], 0.0f);
            }
        }
    }
}

extern "C" void kernel_launch(void* const* d_in, const int* in_sizes, int n_in,
                              void* d_out, int out_size) {
    const float* x = (const float*)d_in[0];
    float* out = (float*)d_out;
    int rows = in_sizes[0] / N_COLS;   // 8192
    topk_fused<<<rows, THREADS>>>(x, out);
}